// round 11
// baseline (speedup 1.0000x reference)
#include <cuda_runtime.h>
#include <cuda_fp16.h>
#include <cstdint>

// Problem: B=4, C=256, HW=4096. S = Q^T K per batch; outputs S[:, :1024, :1024] + argmax rows.
// 3-segment fp16 split (exact to ~1e-6): S = Qhi*Khi + Qhi*Klo + Qlo*Khi.
// Argmax guarded by fp64 re-score of top-2 when gap < GAP_TAU.
// Top-2 running state lives in SMEM (not registers) to keep the mainloop live set small.
#define BATCH   4
#define CDIM    256
#define HWDIM   4096
#define VIS     1024
#define KSPLIT  512            // [hi(256) | lo(256)] halfs per hw-row
#define TILE_M  128
#define TILE_N  128
#define NCHUNKS (HWDIM / TILE_N)        // 32
#define KSTEPS  24                      // 3 segs x 8 k-blocks of 32
#define TOTSTEPS (NCHUNKS * KSTEPS)     // 768
#define STAGE_BYTES 16384               // A 8KB + B 8KB
#define SM_STATE 65536                  // after 4 stages: 256 thr x 8 slots x 16B = 32KB
#define SM_RED  (SM_STATE + 32768)
#define SM_TOTAL (SM_RED + 8192)
#define GAP_TAU 0.05f

// Scratch: transposed + fp16 hi/lo split operands (allocation-free device globals).
__device__ __half g_QT[(size_t)BATCH * HWDIM * KSPLIT];
__device__ __half g_KT[(size_t)BATCH * HWDIM * KSPLIT];

#define CP16(dst, src) \
    asm volatile("cp.async.cg.shared.global [%0], [%1], 16;" :: "r"(dst), "l"(src))
#define CP_COMMIT() asm volatile("cp.async.commit_group;" ::: "memory")
#define CP_WAIT2()  asm volatile("cp.async.wait_group 2;" ::: "memory")

__device__ __forceinline__ uint32_t smem_u32(const void* p) {
    uint32_t a;
    asm("{ .reg .u64 t; cvta.to.shared.u64 t, %1; cvt.u32.u64 %0, t; }" : "=r"(a) : "l"(p));
    return a;
}
__device__ __forceinline__ void ldsm4(uint32_t* r, uint32_t addr) {
    asm volatile("ldmatrix.sync.aligned.m8n8.x4.shared.b16 {%0,%1,%2,%3}, [%4];"
                 : "=r"(r[0]), "=r"(r[1]), "=r"(r[2]), "=r"(r[3]) : "r"(addr));
}
__device__ __forceinline__ void mma16816(float* d, const uint32_t* a, const uint32_t* b) {
    asm volatile("mma.sync.aligned.m16n8k16.row.col.f32.f16.f16.f32 "
                 "{%0,%1,%2,%3}, {%4,%5,%6,%7}, {%8,%9}, {%0,%1,%2,%3};"
                 : "+f"(d[0]), "+f"(d[1]), "+f"(d[2]), "+f"(d[3])
                 : "r"(a[0]), "r"(a[1]), "r"(a[2]), "r"(a[3]), "r"(b[0]), "r"(b[1]));
}
__device__ __forceinline__ void top2_ins(float v, int i, float& v1, int& i1, float& v2, int& i2) {
    if (v > v1 || (v == v1 && i < i1)) { v2 = v1; i2 = i1; v1 = v; i1 = i; }
    else if (v > v2 || (v == v2 && i < i2)) { v2 = v; i2 = i; }
}

// ---- Kernel 1: transpose + fp16 hi/lo split ----
__global__ __launch_bounds__(256, 4)
void split_tp(const float* __restrict__ Q, const float* __restrict__ K)
{
    const int bz = blockIdx.z;                   // bit0 = which tensor, bits1.. = batch
    const float* src = ((bz & 1) ? K : Q) + (size_t)(bz >> 1) * CDIM * HWDIM;
    __half* dst = ((bz & 1) ? g_KT : g_QT) + (size_t)(bz >> 1) * HWDIM * KSPLIT;
    __shared__ float t[32][33];
    const int x0 = blockIdx.x * 32;              // hw
    const int y0 = blockIdx.y * 32;              // c
    const int tx = threadIdx.x & 31, ty = threadIdx.x >> 5;
#pragma unroll
    for (int j = 0; j < 4; ++j)
        t[ty + 8 * j][tx] = src[(size_t)(y0 + ty + 8 * j) * HWDIM + x0 + tx];
    __syncthreads();
#pragma unroll
    for (int j = 0; j < 4; ++j) {
        const int hw = x0 + ty + 8 * j;
        const float x = t[tx][ty + 8 * j];
        const __half hi = __float2half_rn(x);
        const __half lo = __float2half_rn(x - __half2float(hi));
        const size_t o = (size_t)hw * KSPLIT + y0 + tx;
        dst[o] = hi;
        dst[o + CDIM] = lo;
    }
}

// one cp.async stage: A 128x32 halfs (8KB), B 128x32 halfs (8KB), swizzled 64B rows.
__device__ __forceinline__ void issue_stage(
    uint32_t smb, int slot, const __half* QTb, const __half* KTb,
    int chunk, int ks, int soff, int dst0)
{
    const int seg = ks >> 3, kb = ks & 7;
    const int ca = ((seg == 2) ? CDIM : 0) + kb * 32;   // A: [hi | hi | lo]
    const int cb = ((seg == 1) ? CDIM : 0) + kb * 32;   // B: [hi | lo | hi]
    const uint32_t ab = smb + slot * STAGE_BYTES;
    const uint32_t bb = ab + 8192;
    const __half* pa = QTb + soff + ca;
    CP16(ab + dst0, pa);
    CP16(ab + dst0 + 4096, pa + 64 * KSPLIT);
    const __half* pb = KTb + (size_t)chunk * TILE_N * KSPLIT + soff + cb;
    CP16(bb + dst0, pb);
    CP16(bb + dst0 + 4096, pb + 64 * KSPLIT);
}

// ---- Kernel 2: fp16-split mma.sync GEMM + smem-resident top2 + exact fixup ----
__global__ __launch_bounds__(256, 1)
void gemm_fp16(const float* __restrict__ Qo, const float* __restrict__ Ko,
               float* __restrict__ Svis, void* __restrict__ Hout, int hmode)
{
    extern __shared__ char smem[];
    const uint32_t smb = smem_u32(smem);
    const int tid = threadIdx.x;
    const int lane = tid & 31, wid = tid >> 5;
    const int wm = wid >> 2, wn = wid & 3;          // warp grid 2(M) x 4(N), tile 64x32
    const int b = blockIdx.y;
    const int q0 = blockIdx.x * TILE_M;

    const __half* QTb = g_QT + ((size_t)(b * HWDIM + q0)) * KSPLIT;
    const __half* KTb = g_KT + (size_t)b * HWDIM * KSPLIT;

    // cp.async mapping: thread covers unit tid and tid+256 of 512 16B-units.
    const int r0 = tid >> 2, u0 = tid & 3;
    const int soff = r0 * KSPLIT + u0 * 8;
    const int dst0 = r0 * 64 + ((u0 ^ ((r0 >> 1) & 3)) * 16);

    // ldmatrix lane geometry
    const int arow = lane & 15;
    const int auk  = (lane >> 4) & 1;
    const int brow = (lane & 7) + ((lane >> 4) & 1) * 8;
    const int buk  = (lane >> 3) & 1;

    int am[4], axor[4];
#pragma unroll
    for (int mt = 0; mt < 4; ++mt) {
        const int m = wm * 64 + mt * 16 + arow;
        am[mt] = m * 64;
        axor[mt] = (m >> 1) & 3;
    }
    int bn[2], bxor[2];
#pragma unroll
    for (int p = 0; p < 2; ++p) {
        const int n = wn * 32 + p * 16 + brow;
        bn[p] = n * 64;
        bxor[p] = (n >> 1) & 3;
    }

    const float NEG_INF = __int_as_float(0xff800000);

    // SMEM-resident top-2 state: slot s of this thread at SM_STATE + (s*256+tid)*16.
    float4* state = (float4*)(smem + SM_STATE);
#pragma unroll
    for (int s = 0; s < 8; ++s)
        state[s * 256 + tid] = make_float4(NEG_INF, __int_as_float(0),
                                           NEG_INF, __int_as_float(1));

    // Prologue: 3 stages in flight
    int pf_chunk = 0, pf_ks = 0;
#pragma unroll
    for (int s = 0; s < 3; ++s) {
        issue_stage(smb, s, QTb, KTb, pf_chunk, pf_ks, soff, dst0);
        CP_COMMIT();
        if (++pf_ks == KSTEPS) { pf_ks = 0; ++pf_chunk; }
    }

    int gs = 0;
    const bool visq = (q0 < VIS);

    for (int chunk = 0; chunk < NCHUNKS; ++chunk) {
        float acc[4][4][4];
#pragma unroll
        for (int mt = 0; mt < 4; ++mt)
#pragma unroll
        for (int nt = 0; nt < 4; ++nt)
#pragma unroll
        for (int e = 0; e < 4; ++e) acc[mt][nt][e] = 0.f;

        for (int ks = 0; ks < KSTEPS; ++ks, ++gs) {
            CP_WAIT2();
            __syncthreads();
            const int slot = gs & 3;
            const uint32_t ab = smb + slot * STAGE_BYTES;
            const uint32_t bb = ab + 8192;
#pragma unroll
            for (int k16 = 0; k16 < 2; ++k16) {
                uint32_t af[4][4];
#pragma unroll
                for (int mt = 0; mt < 4; ++mt) {
                    const int u = (k16 * 2 + auk) ^ axor[mt];
                    ldsm4(af[mt], ab + am[mt] + u * 16);
                }
                uint32_t bf[2][4];
#pragma unroll
                for (int p = 0; p < 2; ++p) {
                    const int u = (k16 * 2 + buk) ^ bxor[p];
                    ldsm4(bf[p], bb + bn[p] + u * 16);
                }
#pragma unroll
                for (int mt = 0; mt < 4; ++mt)
#pragma unroll
                for (int nt = 0; nt < 4; ++nt)
                    mma16816(acc[mt][nt], af[mt], &bf[nt >> 1][(nt & 1) * 2]);
            }
            if (gs + 3 < TOTSTEPS) {
                issue_stage(smb, (gs + 3) & 3, QTb, KTb, pf_chunk, pf_ks, soff, dst0);
                if (++pf_ks == KSTEPS) { pf_ks = 0; ++pf_chunk; }
            }
            CP_COMMIT();
        }

        // Epilogue: chunk-local top-2 per row slot (transient regs), merge into SMEM state.
        const int n0 = chunk * TILE_N;
#pragma unroll
        for (int mt = 0; mt < 4; ++mt)
#pragma unroll
        for (int h = 0; h < 2; ++h) {
            const int s = mt * 2 + h;
            float lv1 = NEG_INF, lv2 = NEG_INF;
            int   li1 = 0, li2 = 1;
#pragma unroll
            for (int nt = 0; nt < 4; ++nt) {
                const int nb = n0 + wn * 32 + nt * 8 + (lane & 3) * 2;
#pragma unroll
                for (int j = 0; j < 2; ++j)
                    top2_ins(acc[mt][nt][h * 2 + j], nb + j, lv1, li1, lv2, li2);
            }
            float4 st = state[s * 256 + tid];
            float sv1 = st.x, sv2 = st.z;
            int   si1 = __float_as_int(st.y), si2 = __float_as_int(st.w);
            // Insert later-chunk candidates into earlier state (strict > keeps first occurrence).
            top2_ins(lv1, li1, sv1, si1, sv2, si2);
            top2_ins(lv2, li2, sv1, si1, sv2, si2);
            state[s * 256 + tid] = make_float4(sv1, __int_as_float(si1),
                                               sv2, __int_as_float(si2));
        }
        if (visq && n0 < VIS) {
#pragma unroll
            for (int mt = 0; mt < 4; ++mt)
#pragma unroll
            for (int h = 0; h < 2; ++h) {
                const int q = q0 + wm * 64 + mt * 16 + (lane >> 2) + h * 8;
                float* row = Svis + ((size_t)(b * VIS + q)) * VIS;
#pragma unroll
                for (int nt = 0; nt < 4; ++nt) {
                    const int n = n0 + wn * 32 + nt * 8 + (lane & 3) * 2;
                    *(float2*)(row + n) = make_float2(acc[mt][nt][h * 2], acc[mt][nt][h * 2 + 1]);
                }
            }
        }
    }

    // Pull state back into registers for the final reduction.
    float tv1[8], tv2[8];
    int   ti1[8], ti2[8];
#pragma unroll
    for (int s = 0; s < 8; ++s) {
        const float4 st = state[s * 256 + tid];
        tv1[s] = st.x; ti1[s] = __float_as_int(st.y);
        tv2[s] = st.z; ti2[s] = __float_as_int(st.w);
    }
    // Lane reduction: lanes sharing a row differ in bits 0-1 of lane.
#pragma unroll
    for (int s = 0; s < 8; ++s) {
#pragma unroll
        for (int off = 1; off <= 2; off <<= 1) {
            const float ov1 = __shfl_xor_sync(0xffffffffu, tv1[s], off);
            const int   oi1 = __shfl_xor_sync(0xffffffffu, ti1[s], off);
            const float ov2 = __shfl_xor_sync(0xffffffffu, tv2[s], off);
            const int   oi2 = __shfl_xor_sync(0xffffffffu, ti2[s], off);
            top2_ins(ov1, oi1, tv1[s], ti1[s], tv2[s], ti2[s]);
            top2_ins(ov2, oi2, tv1[s], ti1[s], tv2[s], ti2[s]);
        }
    }
    // Cross-warp (4 wn groups) via smem.
    float* mv1 = (float*)(smem + SM_RED);
    int*   mi1 = (int*)(smem + SM_RED + 2048);
    float* mv2 = (float*)(smem + SM_RED + 4096);
    int*   mi2 = (int*)(smem + SM_RED + 6144);
    __syncthreads();
    if ((lane & 3) == 0) {
#pragma unroll
        for (int s = 0; s < 8; ++s) {
            const int mt = s >> 1, h = s & 1;
            const int row = wm * 64 + mt * 16 + (lane >> 2) + h * 8;
            mv1[wn * 128 + row] = tv1[s];
            mi1[wn * 128 + row] = ti1[s];
            mv2[wn * 128 + row] = tv2[s];
            mi2[wn * 128 + row] = ti2[s];
        }
    }
    __syncthreads();
    if (tid < 128) {
        float v1 = mv1[tid], v2 = mv2[tid];
        int   i1 = mi1[tid], i2 = mi2[tid];
#pragma unroll
        for (int w = 1; w < 4; ++w) {
            top2_ins(mv1[w * 128 + tid], mi1[w * 128 + tid], v1, i1, v2, i2);
            top2_ins(mv2[w * 128 + tid], mi2[w * 128 + tid], v1, i1, v2, i2);
        }
        int idx = i1;
        if (v1 - v2 < GAP_TAU) {
            // Exact fp64 re-score of the two candidates from original fp32 data.
            const float* Qc = Qo + (size_t)b * CDIM * HWDIM + (q0 + tid);
            const float* Ka = Ko + (size_t)b * CDIM * HWDIM + i1;
            const float* Kb2 = Ko + (size_t)b * CDIM * HWDIM + i2;
            double e1 = 0.0, e2 = 0.0;
            for (int c = 0; c < CDIM; ++c) {
                const double qv = (double)Qc[(size_t)c * HWDIM];
                e1 += qv * (double)Ka[(size_t)c * HWDIM];
                e2 += qv * (double)Kb2[(size_t)c * HWDIM];
            }
            if (e2 > e1 || (e2 == e1 && i2 < i1)) idx = i2;
        }
        const size_t hq = (size_t)b * HWDIM + q0 + tid;
        if (hmode == 1) ((long long*)Hout)[hq] = (long long)idx;
        else            ((float*)Hout)[hq] = (float)idx;
    }
}

extern "C" void kernel_launch(void* const* d_in, const int* in_sizes, int n_in,
                              void* d_out, int out_size)
{
    const float* Q = (const float*)d_in[0];
    const float* K = (const float*)d_in[1];
    // V unused by reference outputs.

    float* Svis = (float*)d_out;
    const size_t svis_elems = (size_t)BATCH * VIS * VIS;

    int hmode;
    void* hptr;
    if (out_size == 4227072) {
        hmode = 1;
        hptr = (void*)((char*)d_out + svis_elems * sizeof(float));
    } else {
        hmode = 0;
        hptr = (void*)((float*)d_out + svis_elems);
    }

    static int attr_done = 0;
    if (!attr_done) {
        cudaFuncSetAttribute(gemm_fp16, cudaFuncAttributeMaxDynamicSharedMemorySize, SM_TOTAL);
        attr_done = 1;
    }

    split_tp<<<dim3(HWDIM / 32, CDIM / 32, 2 * BATCH), 256>>>(Q, K);
    gemm_fp16<<<dim3(HWDIM / TILE_M, BATCH), 256, SM_TOTAL>>>(Q, K, Svis, hptr, hmode);
}

// round 12
// speedup vs baseline: 1.6483x; 1.6483x over previous
#include <cuda_runtime.h>
#include <cuda_fp16.h>
#include <cstdint>

// Problem: B=4, C=256, HW=4096. S = Q^T K per batch; outputs S[:, :1024, :1024] + argmax rows.
#define BATCH   4
#define CDIM    256
#define HWDIM   4096
#define VIS     1024
#define KSPLIT  512            // [hi(256) | lo(256)] halfs per hw-row
#define TILE_M  128
#define TILE_N  128
#define NCHUNKS (HWDIM / TILE_N)        // 32
#define KSTEPS  24                      // per chunk: K_eff=768 in BK=32 steps
#define TOTSTEPS (NCHUNKS * KSTEPS)     // 768
#define STAGE_BYTES 16384               // A 8KB + B 8KB
#define SM_RED  65536                   // after 4 stages
#define SM_TOTAL (SM_RED + 4096)

// Scratch: transposed + fp16 hi/lo split operands (allocation-free device globals).
__device__ __half g_QT[(size_t)BATCH * HWDIM * KSPLIT];
__device__ __half g_KT[(size_t)BATCH * HWDIM * KSPLIT];

#define CP16(dst, src) \
    asm volatile("cp.async.cg.shared.global [%0], [%1], 16;" :: "r"(dst), "l"(src))
#define CP_COMMIT() asm volatile("cp.async.commit_group;" ::: "memory")
#define CP_WAIT2()  asm volatile("cp.async.wait_group 2;" ::: "memory")

__device__ __forceinline__ uint32_t smem_u32(const void* p) {
    uint32_t a;
    asm("{ .reg .u64 t; cvta.to.shared.u64 t, %1; cvt.u32.u64 %0, t; }" : "=r"(a) : "l"(p));
    return a;
}
__device__ __forceinline__ void ldsm4(uint32_t* r, uint32_t addr) {
    asm volatile("ldmatrix.sync.aligned.m8n8.x4.shared.b16 {%0,%1,%2,%3}, [%4];"
                 : "=r"(r[0]), "=r"(r[1]), "=r"(r[2]), "=r"(r[3]) : "r"(addr));
}
__device__ __forceinline__ void mma16816(float* d, const uint32_t* a, const uint32_t* b) {
    asm volatile("mma.sync.aligned.m16n8k16.row.col.f32.f16.f16.f32 "
                 "{%0,%1,%2,%3}, {%4,%5,%6,%7}, {%8,%9}, {%0,%1,%2,%3};"
                 : "+f"(d[0]), "+f"(d[1]), "+f"(d[2]), "+f"(d[3])
                 : "r"(a[0]), "r"(a[1]), "r"(a[2]), "r"(a[3]), "r"(b[0]), "r"(b[1]));
}

// ---- Kernel 1: transpose + fp16 hi/lo split ----
// src[b][c][hw] fp32 -> dst[b][hw][c]=hi, dst[b][hw][256+c]=lo
__global__ __launch_bounds__(256, 4)
void split_tp(const float* __restrict__ Q, const float* __restrict__ K)
{
    const int bz = blockIdx.z;                   // bit0 = which tensor, bits1.. = batch
    const float* src = ((bz & 1) ? K : Q) + (size_t)(bz >> 1) * CDIM * HWDIM;
    __half* dst = ((bz & 1) ? g_KT : g_QT) + (size_t)(bz >> 1) * HWDIM * KSPLIT;
    __shared__ float t[32][33];
    const int x0 = blockIdx.x * 32;              // hw
    const int y0 = blockIdx.y * 32;              // c
    const int tx = threadIdx.x & 31, ty = threadIdx.x >> 5;
#pragma unroll
    for (int j = 0; j < 4; ++j)
        t[ty + 8 * j][tx] = src[(size_t)(y0 + ty + 8 * j) * HWDIM + x0 + tx];
    __syncthreads();
#pragma unroll
    for (int j = 0; j < 4; ++j) {
        const int hw = x0 + ty + 8 * j;
        const float x = t[tx][ty + 8 * j];
        const __half hi = __float2half_rn(x);
        const __half lo = __float2half_rn(x - __half2float(hi));
        const size_t o = (size_t)hw * KSPLIT + y0 + tx;
        dst[o] = hi;
        dst[o + CDIM] = lo;
    }
}

// issue one cp.async stage: A tile 128x32 halfs, B tile 128x32 halfs, swizzled.
__device__ __forceinline__ void issue_stage(
    uint32_t smb, int slot, const __half* QTb, const __half* KTb,
    int chunk, int ks, int soff /* r0*512+u0*8 */, int dst0 /* swizzled byte off */)
{
    const int seg = ks >> 3, kb = ks & 7;
    const int ca = ((seg == 2) ? CDIM : 0) + kb * 32;   // A: [hi | hi | lo]
    const int cb = ((seg == 1) ? CDIM : 0) + kb * 32;   // B: [hi | lo | hi]
    const uint32_t ab = smb + slot * STAGE_BYTES;
    const uint32_t bb = ab + 8192;
    const __half* pa = QTb + soff + ca;
    CP16(ab + dst0, pa);
    CP16(ab + dst0 + 4096, pa + 64 * KSPLIT);
    const __half* pb = KTb + (size_t)chunk * TILE_N * KSPLIT + soff + cb;
    CP16(bb + dst0, pb);
    CP16(bb + dst0 + 4096, pb + 64 * KSPLIT);
}

// ---- Kernel 2: fp16-split mma.sync GEMM + argmax + visible store ----
__global__ __launch_bounds__(256, 1)
void gemm_fp16(float* __restrict__ Svis, void* __restrict__ Hout, int hmode)
{
    extern __shared__ char smem[];
    const uint32_t smb = smem_u32(smem);
    const int tid = threadIdx.x;
    const int lane = tid & 31, wid = tid >> 5;
    const int wm = wid >> 2, wn = wid & 3;          // warp grid 2(M) x 4(N)
    const int b = blockIdx.y;
    const int q0 = blockIdx.x * TILE_M;

    const __half* QTb = g_QT + ((size_t)(b * HWDIM + q0)) * KSPLIT;
    const __half* KTb = g_KT + (size_t)b * HWDIM * KSPLIT;

    // cp.async mapping: thread covers unit i=tid and i=tid+256 of 512 16B-units.
    const int r0 = tid >> 2, u0 = tid & 3;
    const int soff = r0 * KSPLIT + u0 * 8;
    const int dst0 = r0 * 64 + ((u0 ^ ((r0 >> 1) & 3)) * 16);

    // ldmatrix lane geometry
    const int arow = lane & 15;                 // A x4: rows from lane bits 0-3
    const int auk  = (lane >> 4) & 1;           // A: 16B half of k16 from bit 4
    const int brow = (lane & 7) + ((lane >> 4) & 1) * 8;  // B x4 rows
    const int buk  = (lane >> 3) & 1;           // B: 16B half from bit 3

    int am[4], axor[4];
#pragma unroll
    for (int mt = 0; mt < 4; ++mt) {
        const int m = wm * 64 + mt * 16 + arow;
        am[mt] = m * 64;
        axor[mt] = (m >> 1) & 3;
    }
    int bn[2], bxor[2];
#pragma unroll
    for (int p = 0; p < 2; ++p) {
        const int n = wn * 32 + p * 16 + brow;
        bn[p] = n * 64;
        bxor[p] = (n >> 1) & 3;
    }

    const float NEG_INF = __int_as_float(0xff800000);
    float run_v[8];
    int   run_i[8];
#pragma unroll
    for (int s = 0; s < 8; ++s) { run_v[s] = NEG_INF; run_i[s] = 0; }

    // Prologue: 3 stages in flight
    int pf_chunk = 0, pf_ks = 0;
#pragma unroll
    for (int s = 0; s < 3; ++s) {
        issue_stage(smb, s, QTb, KTb, pf_chunk, pf_ks, soff, dst0);
        CP_COMMIT();
        if (++pf_ks == KSTEPS) { pf_ks = 0; ++pf_chunk; }
    }

    int gs = 0;
    const bool visq = (q0 < VIS);

    for (int chunk = 0; chunk < NCHUNKS; ++chunk) {
        float acc[4][4][4];
#pragma unroll
        for (int mt = 0; mt < 4; ++mt)
#pragma unroll
        for (int nt = 0; nt < 4; ++nt)
#pragma unroll
        for (int e = 0; e < 4; ++e) acc[mt][nt][e] = 0.f;

        for (int ks = 0; ks < KSTEPS; ++ks, ++gs) {
            CP_WAIT2();
            __syncthreads();
            const int slot = gs & 3;
            const uint32_t ab = smb + slot * STAGE_BYTES;
            const uint32_t bb = ab + 8192;
#pragma unroll
            for (int k16 = 0; k16 < 2; ++k16) {
                uint32_t af[4][4];
#pragma unroll
                for (int mt = 0; mt < 4; ++mt) {
                    const int u = (k16 * 2 + auk) ^ axor[mt];
                    ldsm4(af[mt], ab + am[mt] + u * 16);
                }
                uint32_t bf[2][4];
#pragma unroll
                for (int p = 0; p < 2; ++p) {
                    const int u = (k16 * 2 + buk) ^ bxor[p];
                    ldsm4(bf[p], bb + bn[p] + u * 16);
                }
#pragma unroll
                for (int mt = 0; mt < 4; ++mt)
#pragma unroll
                for (int nt = 0; nt < 4; ++nt)
                    mma16816(acc[mt][nt], af[mt], &bf[nt >> 1][(nt & 1) * 2]);
            }
            if (gs + 3 < TOTSTEPS) {
                issue_stage(smb, (gs + 3) & 3, QTb, KTb, pf_chunk, pf_ks, soff, dst0);
                if (++pf_ks == KSTEPS) { pf_ks = 0; ++pf_chunk; }
            }
            CP_COMMIT();
        }

        // Epilogue: argmax update + visible-corner store, straight from fragments.
        const int n0 = chunk * TILE_N;
#pragma unroll
        for (int mt = 0; mt < 4; ++mt)
#pragma unroll
        for (int nt = 0; nt < 4; ++nt) {
            const int nb = n0 + wn * 32 + nt * 8 + (lane & 3) * 2;
#pragma unroll
            for (int h = 0; h < 2; ++h) {
                const int s = mt * 2 + h;
#pragma unroll
                for (int j = 0; j < 2; ++j) {
                    const float v = acc[mt][nt][h * 2 + j];
                    if (v > run_v[s]) { run_v[s] = v; run_i[s] = nb + j; }
                }
            }
        }
        if (visq && n0 < VIS) {
#pragma unroll
            for (int mt = 0; mt < 4; ++mt)
#pragma unroll
            for (int h = 0; h < 2; ++h) {
                const int q = q0 + wm * 64 + mt * 16 + (lane >> 2) + h * 8;
                float* row = Svis + ((size_t)(b * VIS + q)) * VIS;
#pragma unroll
                for (int nt = 0; nt < 4; ++nt) {
                    const int n = n0 + wn * 32 + nt * 8 + (lane & 3) * 2;
                    float2 v2 = make_float2(acc[mt][nt][h * 2], acc[mt][nt][h * 2 + 1]);
                    *(float2*)(row + n) = v2;
                }
            }
        }
    }

    // Reduce argmax: lanes sharing a row differ only in bits 0-1 of lane.
#pragma unroll
    for (int s = 0; s < 8; ++s) {
        float v = run_v[s];
        int idx = run_i[s];
#pragma unroll
        for (int off = 1; off <= 2; off <<= 1) {
            float ov = __shfl_xor_sync(0xffffffffu, v, off);
            int   oi = __shfl_xor_sync(0xffffffffu, idx, off);
            if (ov > v || (ov == v && oi < idx)) { v = ov; idx = oi; }
        }
        run_v[s] = v; run_i[s] = idx;
    }
    float* mv = (float*)(smem + SM_RED);
    int*   mi = (int*)(smem + SM_RED + 2048);
    __syncthreads();
    if ((lane & 3) == 0) {
#pragma unroll
        for (int s = 0; s < 8; ++s) {
            const int mt = s >> 1, h = s & 1;
            const int row = wm * 64 + mt * 16 + (lane >> 2) + h * 8;
            mv[wn * 128 + row] = run_v[s];
            mi[wn * 128 + row] = run_i[s];
        }
    }
    __syncthreads();
    if (tid < 128) {
        float v = mv[tid];
        int idx = mi[tid];
#pragma unroll
        for (int w = 1; w < 4; ++w) {
            const float ov = mv[w * 128 + tid];
            const int   oi = mi[w * 128 + tid];
            if (ov > v || (ov == v && oi < idx)) { v = ov; idx = oi; }
        }
        const size_t hq = (size_t)b * HWDIM + q0 + tid;
        if (hmode == 1) ((long long*)Hout)[hq] = (long long)idx;
        else            ((float*)Hout)[hq] = (float)idx;
    }
}

extern "C" void kernel_launch(void* const* d_in, const int* in_sizes, int n_in,
                              void* d_out, int out_size)
{
    const float* Q = (const float*)d_in[0];
    const float* K = (const float*)d_in[1];
    // V unused by reference outputs.

    float* Svis = (float*)d_out;
    const size_t svis_elems = (size_t)BATCH * VIS * VIS;

    int hmode;
    void* hptr;
    if (out_size == 4227072) {
        hmode = 1;
        hptr = (void*)((char*)d_out + svis_elems * sizeof(float));
    } else {
        hmode = 0;
        hptr = (void*)((float*)d_out + svis_elems);
    }

    static int attr_done = 0;
    if (!attr_done) {
        cudaFuncSetAttribute(gemm_fp16, cudaFuncAttributeMaxDynamicSharedMemorySize, SM_TOTAL);
        attr_done = 1;
    }

    split_tp<<<dim3(HWDIM / 32, CDIM / 32, 2 * BATCH), 256>>>(Q, K);
    gemm_fp16<<<dim3(HWDIM / TILE_M, BATCH), 256, SM_TOTAL>>>(Svis, hptr, hmode);
}